// round 15
// baseline (speedup 1.0000x reference)
#include <cuda_runtime.h>
#include <cstdint>

// Chamfer distance: B=8, N=M=4096, D=3 — exact NN via x-buckets + warp-
// cooperative pruned search (round 15).
//
// d(p,g) = |p|^2 + (|g|^2 - 2 p.g); best = min(|g|^2 - 2 p.g);
// dist = max(|p|^2 + best, 0).  Targets counting-scattered into 512 linear
// x-bins; prune a side when (distance to bucket edge)^2 - |p|^2 >= best
// (one-bucket slack absorbs binning rounding -> exact).  All 32 lanes of a
// warp walk the SAME buckets (broadcast LDS, uniform control, __all_sync
// prune votes); each lane evaluates its own source.

constexpr int B     = 8;
constexpr int NPTS  = 4096;
constexpr int UNITS = 16;                       // arr*8 + b
constexpr int NB    = 512;                      // x buckets
constexpr int BUCKET_THREADS = 512;
constexpr int PPT   = NPTS / BUCKET_THREADS;    // 8 points per thread
constexpr int SEARCH_THREADS = 256;
constexpr int SEARCH_BLOCKS  = UNITS * (NPTS / SEARCH_THREADS); // 256
constexpr int SEARCH_SMEM    = (NPTS + 4) * 16 + (NB + 1) * 4;  // 67652 B

__device__ float4       g_pts[UNITS][NPTS + 4]; // bucket-ordered {x,y,z,|g|^2}
__device__ int          g_bound[UNITS][NB + 1];
__device__ float        g_xmin[UNITS], g_scale[UNITS], g_invw[UNITS];
__device__ float        g_bsum[SEARCH_BLOCKS];
__device__ unsigned int g_cnt;

// ----------------------------------------------------------- bucketize ----
__global__ __launch_bounds__(BUCKET_THREADS) void bucket_kernel(
    const float* __restrict__ pred, const float* __restrict__ gt)
{
    __shared__ int   cnt[NB];
    __shared__ int   boff[NB];
    __shared__ float swmin[BUCKET_THREADS / 32], swmax[BUCKET_THREADS / 32];
    __shared__ float s_xmin, s_scale;

    const int bx  = blockIdx.x;                 // unit
    const int arr = bx >> 3, b = bx & 7;
    const float* pts = (arr == 0 ? pred : gt) + (size_t)b * NPTS * 3;
    const int tid = threadIdx.x, wid = tid >> 5, lid = tid & 31;

    // per-thread x values + min/max
    float mn = 1e30f, mxv = -1e30f;
    float lx[PPT];
    #pragma unroll
    for (int k = 0; k < PPT; ++k) {
        lx[k] = pts[3 * (tid + k * BUCKET_THREADS)];
        mn  = fminf(mn,  lx[k]);
        mxv = fmaxf(mxv, lx[k]);
    }
    #pragma unroll
    for (int o = 16; o; o >>= 1) {
        mn  = fminf(mn,  __shfl_xor_sync(0xffffffffu, mn,  o));
        mxv = fmaxf(mxv, __shfl_xor_sync(0xffffffffu, mxv, o));
    }
    if (lid == 0) { swmin[wid] = mn; swmax[wid] = mxv; }
    cnt[tid] = 0;                               // NB == BUCKET_THREADS
    __syncthreads();
    if (tid == 0) {
        float a = swmin[0], c = swmax[0];
        #pragma unroll
        for (int i = 1; i < BUCKET_THREADS / 32; ++i) {
            a = fminf(a, swmin[i]); c = fmaxf(c, swmax[i]);
        }
        s_xmin  = a;
        s_scale = (float)NB / (c - a + 1e-20f); // x=max maps below NB
    }
    __syncthreads();
    const float xmin = s_xmin, scale = s_scale;

    // histogram
    int bk[PPT];
    #pragma unroll
    for (int k = 0; k < PPT; ++k) {
        int v = (int)((lx[k] - xmin) * scale);
        bk[k] = v < 0 ? 0 : (v > NB - 1 ? NB - 1 : v);
        atomicAdd(&cnt[bk[k]], 1);
    }
    __syncthreads();

    // inclusive scan (Hillis-Steele, read-before-write via syncs)
    for (int o = 1; o < NB; o <<= 1) {
        const int t = (tid >= o) ? cnt[tid - o] : 0;
        __syncthreads();
        cnt[tid] += t;
        __syncthreads();
    }
    g_bound[bx][0]       = 0;
    g_bound[bx][tid + 1] = cnt[tid];
    boff[tid] = (tid == 0) ? 0 : cnt[tid - 1];
    __syncthreads();

    // scatter (intra-bucket order nondeterministic; min is set-exact)
    #pragma unroll
    for (int k = 0; k < PPT; ++k) {
        const int i   = tid + k * BUCKET_THREADS;
        const int pos = atomicAdd(&boff[bk[k]], 1);
        const float x = lx[k];
        const float y = pts[3 * i + 1];
        const float z = pts[3 * i + 2];
        g_pts[bx][pos] = make_float4(x, y, z, fmaf(x, x, fmaf(y, y, z * z)));
    }
    if (tid < 4)                                // sentinels for 4-wide overrun
        g_pts[bx][NPTS + tid] = make_float4(1e20f, 0.f, 0.f, 1e30f);
    if (tid == 0) {
        g_xmin[bx]  = xmin;
        g_scale[bx] = scale;
        g_invw[bx]  = 1.0f / scale;
    }
}

// -------------------------------------------------------------- search ----
__global__ __launch_bounds__(SEARCH_THREADS) void search_kernel(
    float* __restrict__ out)
{
    extern __shared__ char smraw[];
    float4* st = reinterpret_cast<float4*>(smraw);        // NPTS+4
    int*    bnd = reinterpret_cast<int*>(st + NPTS + 4);  // NB+1
    __shared__ float sred[SEARCH_THREADS / 32];
    __shared__ int   s_e;

    const int bx    = blockIdx.x;               // 256 blocks
    const int unit  = bx >> 4;                  // source unit: dir*8+b
    const int chunk = bx & 15;
    const int dir   = unit >> 3, b = unit & 7;
    const int tunit = (1 - dir) * 8 + b;        // target unit
    const int tid   = threadIdx.x, wid = tid >> 5, lid = tid & 31;

    for (int i = tid; i < NPTS + 4; i += SEARCH_THREADS) st[i] = g_pts[tunit][i];
    for (int i = tid; i < NB + 1;  i += SEARCH_THREADS) bnd[i] = g_bound[tunit][i];
    __syncthreads();

    const float xmin = g_xmin[tunit], scale = g_scale[tunit], invw = g_invw[tunit];

    // this lane's source (bucket-ordered -> warp-local buckets)
    const float4 P  = g_pts[unit][chunk * SEARCH_THREADS + tid];
    const float  px = P.x, pw = P.w;
    const float  mx = -2.f * P.x, my = -2.f * P.y, mz = -2.f * P.z;

    int myb = (int)((px - xmin) * scale);
    myb = myb < 0 ? 0 : (myb > NB - 1 ? NB - 1 : myb);
    const int bl = __reduce_min_sync(0xffffffffu, myb);
    const int bh = __reduce_max_sync(0xffffffffu, myb);

    float b0 = 3.4e38f, b1 = 3.4e38f, b2 = 3.4e38f, b3 = 3.4e38f;

    // Broadcast loads (uniform i across warp); overrun <= 3 hits sentinels /
    // neighbor-bucket points (superset min -> still exact).
#define EVAL_RANGE(S, E)                                                     \
    for (int i = (S); i < (E); i += 4) {                                     \
        const float4 G0 = st[i];                                             \
        const float4 G1 = st[i + 1];                                         \
        const float4 G2 = st[i + 2];                                         \
        const float4 G3 = st[i + 3];                                         \
        b0 = fminf(b0, fmaf(mx, G0.x, fmaf(my, G0.y, fmaf(mz, G0.z, G0.w))));\
        b1 = fminf(b1, fmaf(mx, G1.x, fmaf(my, G1.y, fmaf(mz, G1.z, G1.w))));\
        b2 = fminf(b2, fmaf(mx, G2.x, fmaf(my, G2.y, fmaf(mz, G2.z, G2.w))));\
        b3 = fminf(b3, fmaf(mx, G3.x, fmaf(my, G3.y, fmaf(mz, G3.z, G3.w))));\
    }

    // home window: all lanes' buckets
    EVAL_RANGE(bnd[bl], bnd[bh + 1]);
    float best = fminf(fminf(b0, b1), fminf(b2, b3));

    // outward expansion, one bucket per side per step, warp-uniform
    int  kr = bh + 1, kl = bl - 1;
    bool doneR = false, doneL = false;
    while (!(doneR && doneL)) {
        if (!doneR) {
            if (kr >= NB) doneR = true;
            else {
                const float d = fmaxf(fmaf((float)(kr - 1), invw, xmin) - px, 0.f);
                if (__all_sync(0xffffffffu, fmaf(d, d, -pw) >= best)) doneR = true;
                else {
                    EVAL_RANGE(bnd[kr], bnd[kr + 1]);
                    best = fminf(fminf(b0, b1), fminf(b2, b3));
                    ++kr;
                }
            }
        }
        if (!doneL) {
            if (kl < 0) doneL = true;
            else {
                const float d = fmaxf(px - fmaf((float)(kl + 2), invw, xmin), 0.f);
                if (__all_sync(0xffffffffu, fmaf(d, d, -pw) >= best)) doneL = true;
                else {
                    EVAL_RANGE(bnd[kl], bnd[kl + 1]);
                    best = fminf(fminf(b0, b1), fminf(b2, b3));
                    --kl;
                }
            }
        }
    }
#undef EVAL_RANGE

    float sum = fmaxf(pw + best, 0.0f);         // exact NN distance^2

    // block reduction (fixed order -> deterministic)
    #pragma unroll
    for (int off = 16; off; off >>= 1)
        sum += __shfl_down_sync(0xffffffffu, sum, off);
    if (lid == 0) sred[wid] = sum;
    __syncthreads();
    if (wid == 0) {
        float v = (lid < SEARCH_THREADS / 32) ? sred[lid] : 0.0f;
        #pragma unroll
        for (int off = 4; off; off >>= 1)
            v += __shfl_down_sync(0xffffffffu, v, off);
        if (lid == 0) g_bsum[bx] = v;
    }

    // global election: last block sums the 256 partials
    __threadfence();
    if (tid == 0)
        s_e = (atomicAdd(&g_cnt, 1u) == (unsigned)(SEARCH_BLOCKS - 1));
    __syncthreads();
    if (!s_e) return;
    __threadfence();

    {
        float v = __ldcg(&g_bsum[tid]);         // 256 threads, 256 partials
        #pragma unroll
        for (int off = 16; off; off >>= 1)
            v += __shfl_down_sync(0xffffffffu, v, off);
        if (lid == 0) sred[wid] = v;
        __syncthreads();
        if (wid == 0) {
            float t = (lid < SEARCH_THREADS / 32) ? sred[lid] : 0.0f;
            #pragma unroll
            for (int off = 4; off; off >>= 1)
                t += __shfl_down_sync(0xffffffffu, t, off);
            if (lid == 0) {
                out[0] = t * (1.0f / (float)(B * NPTS));
                g_cnt = 0;                      // reset for next graph replay
            }
        }
    }
}

extern "C" void kernel_launch(void* const* d_in, const int* in_sizes, int n_in,
                              void* d_out, int out_size)
{
    const float* pred = (const float*)d_in[0];
    const float* gt   = (const float*)d_in[1];
    float* out        = (float*)d_out;

    cudaFuncSetAttribute(search_kernel,
                         cudaFuncAttributeMaxDynamicSharedMemorySize,
                         SEARCH_SMEM);

    bucket_kernel<<<UNITS, BUCKET_THREADS>>>(pred, gt);
    search_kernel<<<SEARCH_BLOCKS, SEARCH_THREADS, SEARCH_SMEM>>>(out);
}

// round 17
// speedup vs baseline: 2.1752x; 2.1752x over previous
#include <cuda_runtime.h>
#include <cstdint>

// Chamfer distance: B=8, N=M=4096, D=3 — unidirectional brute force at the
// FFMA wall, round 17 (R16 resubmitted after infra failure; unroll 2->4).
// R3's proven inner loop (batched 4x LDS.128 + 16 independent FMA chains)
// reshaped to a single 2-blocks/SM wave of 288 blocks, 32 warps/SM.
//
// min_g |p-g|^2 = x2(p) + min_g(w(g) - 2 p.g); clamp at finalize
// (max commutes with min).

constexpr int B       = 8;
constexpr int NPTS    = 4096;
constexpr int THREADS = 512;
constexpr int R       = 4;                     // srcs per thread
constexpr int SRC_PER_BLOCK = THREADS * R;     // 2048
constexpr int SCH     = NPTS / SRC_PER_BLOCK;  // 2 src chunks
constexpr int UNITS   = 16;                    // dir*8 + b
constexpr int TSPLIT  = 9;                     // target splits
constexpr int TT      = 456;                   // targets staged (456*9=4104)
constexpr int NBLOCKS = UNITS * TSPLIT * SCH;  // 288 = 2/SM x 144 SMs

constexpr int FBLOCKS  = 128;
constexpr int FTHREADS = 512;                  // 128*512 = 65536 = UNITS*NPTS

__device__ float        g_part[UNITS][TSPLIT][NPTS];  // unclamped partials
__device__ float        g_fsum[FBLOCKS];
__device__ unsigned int g_cnt;

__global__ __launch_bounds__(THREADS, 2) void chamfer_main(
    const float* __restrict__ pred, const float* __restrict__ gt)
{
    __shared__ float4 s[TT];                   // {x,y,z,|g|^2}  7296B

    const int bx   = blockIdx.x;
    const int unit = bx / (TSPLIT * SCH);
    const int rem  = bx - unit * (TSPLIT * SCH);
    const int ts   = rem >> 1;                 // 0..8
    const int sc   = rem & 1;                  // 0..1
    const int dir  = unit >> 3;
    const int b    = unit & 7;
    const int tid  = threadIdx.x;

    const float* __restrict__ src = (dir == 0) ? pred : gt;
    const float* __restrict__ tgt = (dir == 0) ? gt   : pred;
    const float* sp = src + (size_t)b * NPTS * 3;
    const float* tp = tgt + (size_t)b * NPTS * 3;

    // ---- stage TT targets (pad tail with large-w dummies) ----
    if (tid < TT) {
        const int gi = ts * TT + tid;
        if (gi < NPTS) {
            const float gx = tp[3 * gi + 0];
            const float gy = tp[3 * gi + 1];
            const float gz = tp[3 * gi + 2];
            s[tid] = make_float4(gx, gy, gz,
                                 fmaf(gx, gx, fmaf(gy, gy, gz * gz)));
        } else {
            s[tid] = make_float4(0.f, 0.f, 0.f, 1e30f);
        }
    }

    // ---- load R src points ----
    const int s0 = sc * SRC_PER_BLOCK + tid;
    float mx[R], my[R], mz[R], x2[R], bmin[R];
    #pragma unroll
    for (int k = 0; k < R; ++k) {
        const float* p = sp + (size_t)(s0 + k * THREADS) * 3;
        const float px = p[0], py = p[1], pz = p[2];
        x2[k]   = fmaf(px, px, fmaf(py, py, pz * pz));
        mx[k]   = -2.0f * px;
        my[k]   = -2.0f * py;
        mz[k]   = -2.0f * pz;
        bmin[k] = 3.4e38f;
    }
    __syncthreads();

    // ---- main loop: 456 targets, 4 at a time (R3's proven form) ----
    #pragma unroll 4
    for (int j = 0; j < TT; j += 4) {
        const float4 G0 = s[j + 0];
        const float4 G1 = s[j + 1];
        const float4 G2 = s[j + 2];
        const float4 G3 = s[j + 3];
        #pragma unroll
        for (int k = 0; k < R; ++k) {
            const float d0 = fmaf(mx[k], G0.x, fmaf(my[k], G0.y, fmaf(mz[k], G0.z, G0.w)));
            const float d1 = fmaf(mx[k], G1.x, fmaf(my[k], G1.y, fmaf(mz[k], G1.z, G1.w)));
            const float d2 = fmaf(mx[k], G2.x, fmaf(my[k], G2.y, fmaf(mz[k], G2.z, G2.w)));
            const float d3 = fmaf(mx[k], G3.x, fmaf(my[k], G3.y, fmaf(mz[k], G3.z, G3.w)));
            bmin[k] = fminf(bmin[k], fminf(fminf(d0, d1), fminf(d2, d3)));
        }
    }

    // ---- unclamped partial per src (coalesced) ----
    #pragma unroll
    for (int k = 0; k < R; ++k)
        g_part[unit][ts][s0 + k * THREADS] = x2[k] + bmin[k];
}

__global__ __launch_bounds__(FTHREADS) void chamfer_finalize(
    float* __restrict__ out)
{
    __shared__ float sred[FTHREADS / 32];
    __shared__ int   s_e;

    const int bx  = blockIdx.x;
    const int tid = threadIdx.x;
    const int wid = tid >> 5, lid = tid & 31;

    const int gid  = bx * FTHREADS + tid;      // 0..65535
    const int unit = gid >> 12;
    const int i    = gid & (NPTS - 1);

    // min over 9 target slices, clamp
    float m = __ldcg(&g_part[unit][0][i]);
    #pragma unroll
    for (int t = 1; t < TSPLIT; ++t)
        m = fminf(m, __ldcg(&g_part[unit][t][i]));
    float v = fmaxf(m, 0.0f);

    // block reduce (fixed order)
    #pragma unroll
    for (int off = 16; off; off >>= 1)
        v += __shfl_down_sync(0xffffffffu, v, off);
    if (lid == 0) sred[wid] = v;
    __syncthreads();
    if (wid == 0) {
        float t = (lid < FTHREADS / 32) ? sred[lid] : 0.0f;
        #pragma unroll
        for (int off = 8; off; off >>= 1)
            t += __shfl_down_sync(0xffffffffu, t, off);
        if (lid == 0) g_fsum[bx] = t;
    }

    // election: last block sums the 128 partials
    __threadfence();
    if (tid == 0)
        s_e = (atomicAdd(&g_cnt, 1u) == (unsigned)(FBLOCKS - 1));
    __syncthreads();
    if (!s_e) return;
    __threadfence();

    if (wid < 4) {                             // 128 entries, 4 warps
        float v2 = (tid < FBLOCKS) ? __ldcg(&g_fsum[tid]) : 0.0f;
        #pragma unroll
        for (int off = 16; off; off >>= 1)
            v2 += __shfl_down_sync(0xffffffffu, v2, off);
        if (lid == 0) sred[wid] = v2;
    }
    __syncthreads();
    if (tid == 0) {
        const float tot = (sred[0] + sred[1]) + (sred[2] + sred[3]);
        out[0] = tot * (1.0f / (float)(B * NPTS));
        g_cnt = 0;                             // reset for next graph replay
    }
}

extern "C" void kernel_launch(void* const* d_in, const int* in_sizes, int n_in,
                              void* d_out, int out_size)
{
    const float* pred = (const float*)d_in[0];
    const float* gt   = (const float*)d_in[1];
    float* out        = (float*)d_out;

    chamfer_main<<<NBLOCKS, THREADS>>>(pred, gt);
    chamfer_finalize<<<FBLOCKS, FTHREADS>>>(out);
}